// round 15
// baseline (speedup 1.0000x reference)
#include <cuda_runtime.h>
#include <cuda_fp16.h>
#include <cstdint>

// Problem constants (fixed by the dataset)
constexpr int N  = 50000;
constexpr int E  = 800000;
constexpr int R  = 3;
constexpr int FHID = 128;
constexpr int FOUT = 64;
constexpr int RN = R * N;
constexpr int RE = R * E;

constexpr int N_HALF = 25088;   // split point (multiple of 128)

constexpr int SCAN_BLK = 512;
constexpr int NSCAN = (RN + SCAN_BLK - 1) / SCAN_BLK;   // 293

// Scratch (device globals; no allocation allowed)
__device__ int    g_dego[RN];                       // edge-only out-degree
__device__ int    g_degi[RN];                       // edge-only in-degree
__device__ int    g_off[RN + 1];
__device__ int    g_cur[RN];
__device__ int    g_part[RN];
__device__ int    g_bsum[SCAN_BLK];
__device__ int    g_eidx[RE];                       // CSR: src per (rel,dst)-bin
__device__ __half g_xw1h[(size_t)R * N * FHID];     // 38.4 MB (pre-scaled by rso)
__device__ float  g_acc[(size_t)N * FHID];          // 25.6 MB
__device__ __half g_xw2h[(size_t)R * N * FOUT];     // 19.2 MB (pre-scaled by rso)

// Side stream + events (host objects, created at load).
static cudaStream_t g_s1 = nullptr;
static cudaEvent_t  g_evA = nullptr, g_evB = nullptr, g_evC = nullptr, g_evD = nullptr;
namespace {
struct StreamInit {
    StreamInit() {
        cudaStreamCreateWithFlags(&g_s1, cudaStreamNonBlocking);
        cudaEventCreateWithFlags(&g_evA, cudaEventDisableTiming);
        cudaEventCreateWithFlags(&g_evB, cudaEventDisableTiming);
        cudaEventCreateWithFlags(&g_evC, cudaEventDisableTiming);
        cudaEventCreateWithFlags(&g_evD, cudaEventDisableTiming);
    }
} g_streaminit;
}

// ---------------- degrees ----------------
__global__ void k_deg_count(const int* __restrict__ src, const int* __restrict__ dst) {
    int i = blockIdx.x * blockDim.x + threadIdx.x;
    if (i < RE) {
        int r = i / E;
        atomicAdd(&g_dego[r * N + src[i]], 1);
        atomicAdd(&g_degi[r * N + dst[i]], 1);
    }
}

// ---------------- CSR build ----------------
__global__ __launch_bounds__(SCAN_BLK) void k_scan1() {
    __shared__ int s[SCAN_BLK];
    int t = threadIdx.x;
    int i = blockIdx.x * SCAN_BLK + t;
    int v = (i < RN) ? g_degi[i] : 0;
    s[t] = v;
    __syncthreads();
#pragma unroll
    for (int off = 1; off < SCAN_BLK; off <<= 1) {
        int u = (t >= off) ? s[t - off] : 0;
        __syncthreads();
        s[t] += u;
        __syncthreads();
    }
    if (i < RN) g_part[i] = s[t];
    if (t == SCAN_BLK - 1) g_bsum[blockIdx.x] = s[t];
}

__global__ __launch_bounds__(SCAN_BLK) void k_scan23() {
    __shared__ int s[SCAN_BLK];
    int t = threadIdx.x, bid = blockIdx.x;
    s[t] = (t < bid && t < NSCAN) ? g_bsum[t] : 0;
    __syncthreads();
#pragma unroll
    for (int off = SCAN_BLK / 2; off > 0; off >>= 1) {
        if (t < off) s[t] += s[t + off];
        __syncthreads();
    }
    int blockpref = s[0];
    int i = bid * SCAN_BLK + t;
    if (i < RN) {
        int excl = g_part[i] - g_degi[i] + blockpref;
        g_off[i] = excl;
        g_cur[i] = excl;
    }
    if (i == 0) g_off[RN] = RE;
}

__global__ void k_fill(const int* __restrict__ src, const int* __restrict__ dst) {
    int i = blockIdx.x * blockDim.x + threadIdx.x;
    if (i < RE) {
        int r = i / E;
        int pos = atomicAdd(&g_cur[r * N + dst[i]], 1);
        g_eidx[pos] = src[i];
    }
}

// ---------------- tf32 helpers ----------------
__device__ __forceinline__ uint32_t f2tf(float f) {
    uint32_t u;
    asm("cvt.rna.tf32.f32 %0, %1;" : "=r"(u) : "f"(f));
    return u;
}

__device__ __forceinline__ void mma_tf32(float* d,
        uint32_t a0, uint32_t a1, uint32_t a2, uint32_t a3,
        uint32_t b0, uint32_t b1) {
    asm volatile(
        "mma.sync.aligned.m16n8k8.row.col.f32.tf32.tf32.f32 "
        "{%0,%1,%2,%3}, {%4,%5,%6,%7}, {%8,%9}, {%0,%1,%2,%3};"
        : "+f"(d[0]), "+f"(d[1]), "+f"(d[2]), "+f"(d[3])
        : "r"(a0), "r"(a1), "r"(a2), "r"(a3), "r"(b0), "r"(b1));
}

// inline degree scaling: rsqrt(edge_degree + 1)
__device__ __forceinline__ float degscale(const int* deg, int idx) {
    return rsqrtf((float)(deg[idx] + 1));
}

// ---------------- tf32 GEMM F=128 -> fp16 out, pre-scaled by rso (inline) --------------
template<bool RELU>
__global__ __launch_bounds__(256)
void gemm_tc128(const float* __restrict__ A, const float* __restrict__ Wb,
                __half* __restrict__ Cb, int nrows) {
    constexpr int K = 128, BK = 32;
    const int r = blockIdx.y;
    const float* B = Wb + (size_t)r * K * 128;
    __half* C = Cb + (size_t)r * nrows * 128;
    const int row0 = blockIdx.x * 128;
    const int t = threadIdx.x;
    const int warp = t >> 5, lane = t & 31;
    const int qr = lane >> 2, qc = lane & 3;
    const int wm = (warp & 3) * 32;
    const int wn = (warp >> 2) * 64;

    __shared__ uint32_t sA[128][BK + 4];
    __shared__ uint32_t sB[BK][128 + 8];

    float acc[2][8][4];
#pragma unroll
    for (int i = 0; i < 2; i++)
#pragma unroll
        for (int j = 0; j < 8; j++)
#pragma unroll
            for (int q = 0; q < 4; q++) acc[i][j][q] = 0.f;

    const int am = t >> 1;
    const int ak = (t & 1) * 16;
    const int bkr = t >> 3;
    const int bnc = (t & 7) * 16;

    for (int k0 = 0; k0 < K; k0 += BK) {
        {
            int grow = row0 + am;
#pragma unroll
            for (int q = 0; q < 4; q++) {
                float4 v = make_float4(0.f, 0.f, 0.f, 0.f);
                if (grow < nrows)
                    v = *(const float4*)(A + (size_t)grow * K + k0 + ak + q * 4);
                if (RELU) {
                    v.x = fmaxf(v.x, 0.f); v.y = fmaxf(v.y, 0.f);
                    v.z = fmaxf(v.z, 0.f); v.w = fmaxf(v.w, 0.f);
                }
                uint4 u = make_uint4(f2tf(v.x), f2tf(v.y), f2tf(v.z), f2tf(v.w));
                *(uint4*)&sA[am][ak + q * 4] = u;
            }
        }
        {
#pragma unroll
            for (int q = 0; q < 4; q++) {
                float4 v = *(const float4*)(B + (size_t)(k0 + bkr) * 128 + bnc + q * 4);
                uint4 u = make_uint4(f2tf(v.x), f2tf(v.y), f2tf(v.z), f2tf(v.w));
                *(uint4*)&sB[bkr][bnc + q * 4] = u;
            }
        }
        __syncthreads();
#pragma unroll
        for (int kf = 0; kf < 4; kf++) {
            const int kb = kf * 8;
            uint32_t a[2][4];
#pragma unroll
            for (int mf = 0; mf < 2; mf++) {
                int rr = wm + mf * 16 + qr;
                a[mf][0] = sA[rr][kb + qc];
                a[mf][1] = sA[rr + 8][kb + qc];
                a[mf][2] = sA[rr][kb + qc + 4];
                a[mf][3] = sA[rr + 8][kb + qc + 4];
            }
#pragma unroll
            for (int nf = 0; nf < 8; nf++) {
                int nn = wn + nf * 8 + qr;
                uint32_t b0 = sB[kb + qc][nn];
                uint32_t b1 = sB[kb + qc + 4][nn];
                mma_tf32(acc[0][nf], a[0][0], a[0][1], a[0][2], a[0][3], b0, b1);
                mma_tf32(acc[1][nf], a[1][0], a[1][1], a[1][2], a[1][3], b0, b1);
            }
        }
        __syncthreads();
    }
#pragma unroll
    for (int mf = 0; mf < 2; mf++) {
        int r0g = row0 + wm + mf * 16 + qr;
        int r1g = r0g + 8;
        float s0 = (r0g < nrows) ? degscale(g_dego, r * N + r0g) : 0.f;
        float s1 = (r1g < nrows) ? degscale(g_dego, r * N + r1g) : 0.f;
#pragma unroll
        for (int nf = 0; nf < 8; nf++) {
            int col = wn + nf * 8 + qc * 2;
            if (r0g < nrows)
                *(__half2*)(C + (size_t)r0g * 128 + col) =
                    __floats2half2_rn(acc[mf][nf][0] * s0, acc[mf][nf][1] * s0);
            if (r1g < nrows)
                *(__half2*)(C + (size_t)r1g * 128 + col) =
                    __floats2half2_rn(acc[mf][nf][2] * s1, acc[mf][nf][3] * s1);
        }
    }
}

// ---------------- tf32 GEMM F=64 -> fp16 out, pre-scaled by rso (row_base offset) ------
template<bool RELU>
__global__ __launch_bounds__(256)
void gemm_tc64(const float* __restrict__ A, const float* __restrict__ Wb,
               __half* __restrict__ Cb, int nrows, int row_base) {
    constexpr int K = 128, BK = 32;
    const int r = blockIdx.y;
    const float* B = Wb + (size_t)r * K * 64;
    __half* C = Cb + (size_t)r * nrows * 64;
    const int row0 = row_base + blockIdx.x * 128;
    const int t = threadIdx.x;
    const int warp = t >> 5, lane = t & 31;
    const int qr = lane >> 2, qc = lane & 3;
    const int wm = (warp & 3) * 32;
    const int wn = (warp >> 2) * 32;

    __shared__ uint32_t sA[128][BK + 4];
    __shared__ uint32_t sB[BK][64 + 8];

    float acc[2][4][4];
#pragma unroll
    for (int i = 0; i < 2; i++)
#pragma unroll
        for (int j = 0; j < 4; j++)
#pragma unroll
            for (int q = 0; q < 4; q++) acc[i][j][q] = 0.f;

    const int am = t >> 1;
    const int ak = (t & 1) * 16;
    const int bkrow = t >> 3;
    const int bncol = (t & 7) * 8;

    for (int k0 = 0; k0 < K; k0 += BK) {
        {
            int grow = row0 + am;
#pragma unroll
            for (int q = 0; q < 4; q++) {
                float4 v = make_float4(0.f, 0.f, 0.f, 0.f);
                if (grow < nrows)
                    v = *(const float4*)(A + (size_t)grow * K + k0 + ak + q * 4);
                if (RELU) {
                    v.x = fmaxf(v.x, 0.f); v.y = fmaxf(v.y, 0.f);
                    v.z = fmaxf(v.z, 0.f); v.w = fmaxf(v.w, 0.f);
                }
                uint4 u = make_uint4(f2tf(v.x), f2tf(v.y), f2tf(v.z), f2tf(v.w));
                *(uint4*)&sA[am][ak + q * 4] = u;
            }
        }
        {
#pragma unroll
            for (int q = 0; q < 2; q++) {
                float4 v = *(const float4*)(B + (size_t)(k0 + bkrow) * 64 + bncol + q * 4);
                uint4 u = make_uint4(f2tf(v.x), f2tf(v.y), f2tf(v.z), f2tf(v.w));
                *(uint4*)&sB[bkrow][bncol + q * 4] = u;
            }
        }
        __syncthreads();
#pragma unroll
        for (int kf = 0; kf < 4; kf++) {
            const int kb = kf * 8;
            uint32_t a[2][4];
#pragma unroll
            for (int mf = 0; mf < 2; mf++) {
                int rr = wm + mf * 16 + qr;
                a[mf][0] = sA[rr][kb + qc];
                a[mf][1] = sA[rr + 8][kb + qc];
                a[mf][2] = sA[rr][kb + qc + 4];
                a[mf][3] = sA[rr + 8][kb + qc + 4];
            }
#pragma unroll
            for (int nf = 0; nf < 4; nf++) {
                int nn = wn + nf * 8 + qr;
                uint32_t b0 = sB[kb + qc][nn];
                uint32_t b1 = sB[kb + qc + 4][nn];
                mma_tf32(acc[0][nf], a[0][0], a[0][1], a[0][2], a[0][3], b0, b1);
                mma_tf32(acc[1][nf], a[1][0], a[1][1], a[1][2], a[1][3], b0, b1);
            }
        }
        __syncthreads();
    }
#pragma unroll
    for (int mf = 0; mf < 2; mf++) {
        int r0g = row0 + wm + mf * 16 + qr;
        int r1g = r0g + 8;
        float s0 = (r0g < nrows) ? degscale(g_dego, r * N + r0g) : 0.f;
        float s1 = (r1g < nrows) ? degscale(g_dego, r * N + r1g) : 0.f;
#pragma unroll
        for (int nf = 0; nf < 4; nf++) {
            int col = wn + nf * 8 + qc * 2;
            if (r0g < nrows)
                *(__half2*)(C + (size_t)r0g * 64 + col) =
                    __floats2half2_rn(acc[mf][nf][0] * s0, acc[mf][nf][1] * s0);
            if (r1g < nrows)
                *(__half2*)(C + (size_t)r1g * 64 + col) =
                    __floats2half2_rn(acc[mf][nf][2] * s1, acc[mf][nf][3] * s1);
        }
    }
}

// ---------------- fused gather + selfloop + bias, F=128 (r7 form; node range) ----------
__global__ __launch_bounds__(256)
void k_gather128(const __half* __restrict__ xw, const float* __restrict__ b,
                 float* __restrict__ out, int w_base, int w_end) {
    int w = w_base + ((blockIdx.x * blockDim.x + threadIdx.x) >> 5);
    int lane = threadIdx.x & 31;
    if (w >= w_end) return;
    int c = lane * 4;

    float4 b0 = *(const float4*)(b + 0 * FHID + c);
    float4 b1 = *(const float4*)(b + 1 * FHID + c);
    float4 b2 = *(const float4*)(b + 2 * FHID + c);
    float4 tot = make_float4(b0.x + b1.x + b2.x, b0.y + b1.y + b2.y,
                             b0.z + b1.z + b2.z, b0.w + b1.w + b2.w);

#pragma unroll
    for (int r = 0; r < R; r++) {
        const int bin = r * N + w;
        const __half* base = xw + (size_t)r * N * FHID;
        float4 a = make_float4(0.f, 0.f, 0.f, 0.f);
        int j0 = g_off[bin], j1 = g_off[bin + 1];
        int j = j0;
        for (; j + 4 <= j1; j += 4) {
            int s0 = __ldg(&g_eidx[j + 0]);
            int s1 = __ldg(&g_eidx[j + 1]);
            int s2 = __ldg(&g_eidx[j + 2]);
            int s3 = __ldg(&g_eidx[j + 3]);
            uint2 u0 = *(const uint2*)(base + (size_t)s0 * FHID + c);
            uint2 u1 = *(const uint2*)(base + (size_t)s1 * FHID + c);
            uint2 u2 = *(const uint2*)(base + (size_t)s2 * FHID + c);
            uint2 u3 = *(const uint2*)(base + (size_t)s3 * FHID + c);
#pragma unroll
            for (int p = 0; p < 4; p++) {
                uint2 u = (p == 0) ? u0 : (p == 1) ? u1 : (p == 2) ? u2 : u3;
                float2 f0 = __half22float2(*reinterpret_cast<__half2*>(&u.x));
                float2 f1 = __half22float2(*reinterpret_cast<__half2*>(&u.y));
                a.x += f0.x; a.y += f0.y; a.z += f1.x; a.w += f1.y;
            }
        }
        for (; j < j1; j++) {
            int s = __ldg(&g_eidx[j]);
            uint2 u = *(const uint2*)(base + (size_t)s * FHID + c);
            float2 f0 = __half22float2(*reinterpret_cast<__half2*>(&u.x));
            float2 f1 = __half22float2(*reinterpret_cast<__half2*>(&u.y));
            a.x += f0.x; a.y += f0.y; a.z += f1.x; a.w += f1.y;
        }
        // self-loop: pre-scaled row already carries rso[w]
        {
            uint2 u = *(const uint2*)(base + (size_t)w * FHID + c);
            float2 f0 = __half22float2(*reinterpret_cast<__half2*>(&u.x));
            float2 f1 = __half22float2(*reinterpret_cast<__half2*>(&u.y));
            a.x += f0.x; a.y += f0.y; a.z += f1.x; a.w += f1.y;
        }
        float ri = degscale(g_degi, bin);
        tot.x = fmaf(ri, a.x, tot.x); tot.y = fmaf(ri, a.y, tot.y);
        tot.z = fmaf(ri, a.z, tot.z); tot.w = fmaf(ri, a.w, tot.w);
    }
    *(float4*)(out + (size_t)w * FHID + c) = tot;
}

// ---------------- fused gather + selfloop + bias, F=64 (r7 form: 2 nodes/warp) ---------
__global__ __launch_bounds__(256)
void k_gather64(const __half* __restrict__ xw, const float* __restrict__ b,
                float* __restrict__ out) {
    int warp = (blockIdx.x * blockDim.x + threadIdx.x) >> 5;
    int lane = threadIdx.x & 31;
    int w = warp * 2 + (lane >> 4);
    if (w >= N) return;
    int c = (lane & 15) * 4;

    float4 b0 = *(const float4*)(b + 0 * FOUT + c);
    float4 b1 = *(const float4*)(b + 1 * FOUT + c);
    float4 b2 = *(const float4*)(b + 2 * FOUT + c);
    float4 tot = make_float4(b0.x + b1.x + b2.x, b0.y + b1.y + b2.y,
                             b0.z + b1.z + b2.z, b0.w + b1.w + b2.w);

#pragma unroll
    for (int r = 0; r < R; r++) {
        const int bin = r * N + w;
        const __half* base = xw + (size_t)r * N * FOUT;
        float4 a = make_float4(0.f, 0.f, 0.f, 0.f);
        int j0 = g_off[bin], j1 = g_off[bin + 1];
        int j = j0;
        for (; j + 4 <= j1; j += 4) {
            int s0 = __ldg(&g_eidx[j + 0]);
            int s1 = __ldg(&g_eidx[j + 1]);
            int s2 = __ldg(&g_eidx[j + 2]);
            int s3 = __ldg(&g_eidx[j + 3]);
            uint2 u0 = *(const uint2*)(base + (size_t)s0 * FOUT + c);
            uint2 u1 = *(const uint2*)(base + (size_t)s1 * FOUT + c);
            uint2 u2 = *(const uint2*)(base + (size_t)s2 * FOUT + c);
            uint2 u3 = *(const uint2*)(base + (size_t)s3 * FOUT + c);
#pragma unroll
            for (int p = 0; p < 4; p++) {
                uint2 u = (p == 0) ? u0 : (p == 1) ? u1 : (p == 2) ? u2 : u3;
                float2 f0 = __half22float2(*reinterpret_cast<__half2*>(&u.x));
                float2 f1 = __half22float2(*reinterpret_cast<__half2*>(&u.y));
                a.x += f0.x; a.y += f0.y; a.z += f1.x; a.w += f1.y;
            }
        }
        for (; j < j1; j++) {
            int s = __ldg(&g_eidx[j]);
            uint2 u = *(const uint2*)(base + (size_t)s * FOUT + c);
            float2 f0 = __half22float2(*reinterpret_cast<__half2*>(&u.x));
            float2 f1 = __half22float2(*reinterpret_cast<__half2*>(&u.y));
            a.x += f0.x; a.y += f0.y; a.z += f1.x; a.w += f1.y;
        }
        {
            uint2 u = *(const uint2*)(base + (size_t)w * FOUT + c);
            float2 f0 = __half22float2(*reinterpret_cast<__half2*>(&u.x));
            float2 f1 = __half22float2(*reinterpret_cast<__half2*>(&u.y));
            a.x += f0.x; a.y += f0.y; a.z += f1.x; a.w += f1.y;
        }
        float ri = degscale(g_degi, bin);
        tot.x = fmaf(ri, a.x, tot.x); tot.y = fmaf(ri, a.y, tot.y);
        tot.z = fmaf(ri, a.z, tot.z); tot.w = fmaf(ri, a.w, tot.w);
    }
    *(float4*)(out + (size_t)w * FOUT + c) = tot;
}

// ---------------- launch ----------------
extern "C" void kernel_launch(void* const* d_in, const int* in_sizes, int n_in,
                              void* d_out, int out_size) {
    const float* x   = (const float*)d_in[0];
    const int*   src = (const int*)d_in[1];
    const int*   dst = (const int*)d_in[2];
    const float* W1  = (const float*)d_in[3];
    const float* b1  = (const float*)d_in[4];
    const float* W2  = (const float*)d_in[5];
    const float* b2  = (const float*)d_in[6];
    float* out = (float*)d_out;

    __half *xw1, *xw2;
    float *acc;
    int *dego, *degi;
    cudaGetSymbolAddress((void**)&xw1, g_xw1h);
    cudaGetSymbolAddress((void**)&acc, g_acc);
    cudaGetSymbolAddress((void**)&xw2, g_xw2h);
    cudaGetSymbolAddress((void**)&dego, g_dego);
    cudaGetSymbolAddress((void**)&degi, g_degi);

    const bool fork = (g_s1 != nullptr && g_evA != nullptr && g_evB != nullptr &&
                       g_evC != nullptr && g_evD != nullptr);
    cudaStream_t sb = fork ? g_s1 : (cudaStream_t)0;

    // degrees (main stream)
    cudaMemsetAsync(dego, 0, RN * sizeof(int), 0);
    cudaMemsetAsync(degi, 0, RN * sizeof(int), 0);
    k_deg_count<<<(RE + 255) / 256, 256>>>(src, dst);

    // fork: CSR build (scan + fill) on side stream, overlapped with GEMM1
    if (fork) {
        cudaEventRecord(g_evA, 0);
        cudaStreamWaitEvent(sb, g_evA, 0);
    }
    k_scan1<<<NSCAN, SCAN_BLK, 0, sb>>>();
    k_scan23<<<NSCAN, SCAN_BLK, 0, sb>>>();
    k_fill<<<(RE + 255) / 256, 256, 0, sb>>>(src, dst);
    if (fork) cudaEventRecord(g_evB, sb);

    // main stream: GEMM1 (degree scaling inline in epilogue)
    dim3 gg((N + 127) / 128, R);
    gemm_tc128<false><<<gg, 256>>>(x, W1, xw1, N);

    // join: gathers need the CSR
    if (fork) cudaStreamWaitEvent((cudaStream_t)0, g_evB, 0);

    // gather128 half 0: nodes [0, N_HALF)
    {
        int nwarp = N_HALF;
        k_gather128<<<(nwarp * 32 + 255) / 256, 256>>>(xw1, b1, acc, 0, N_HALF);
    }

    if (fork) {
        // side stream: gemm64 on rows [0, N_HALF) overlapped with gather128 half 1
        cudaEventRecord(g_evC, 0);
        cudaStreamWaitEvent(sb, g_evC, 0);
        dim3 g0(N_HALF / 128, R);
        gemm_tc64<true><<<g0, 256, 0, sb>>>(acc, W2, xw2, N, 0);
        cudaEventRecord(g_evD, sb);

        // main stream: gather128 half 1
        int nwarp = N - N_HALF;
        k_gather128<<<(nwarp * 32 + 255) / 256, 256>>>(xw1, b1, acc, N_HALF, N);

        // main stream: gemm64 on remaining rows
        cudaStreamWaitEvent((cudaStream_t)0, g_evD, 0);
        dim3 g1((N - N_HALF + 127) / 128, R);
        gemm_tc64<true><<<g1, 256>>>(acc, W2, xw2, N, N_HALF);
    } else {
        int nwarp = N - N_HALF;
        k_gather128<<<(nwarp * 32 + 255) / 256, 256>>>(xw1, b1, acc, N_HALF, N);
        dim3 g1((N + 127) / 128, R);
        gemm_tc64<true><<<g1, 256>>>(acc, W2, xw2, N, 0);
    }

    // layer-2 gather
    k_gather64<<<(N * 16 + 255) / 256, 256>>>(xw2, b2, out);
}

// round 16
// speedup vs baseline: 1.0244x; 1.0244x over previous
#include <cuda_runtime.h>
#include <cuda_fp16.h>
#include <cstdint>

// Problem constants (fixed by the dataset)
constexpr int N  = 50000;
constexpr int E  = 800000;
constexpr int R  = 3;
constexpr int FHID = 128;
constexpr int FOUT = 64;
constexpr int RN = R * N;
constexpr int RE = R * E;

constexpr int SCAN_BLK = 512;
constexpr int NSCAN = (RN + SCAN_BLK - 1) / SCAN_BLK;   // 293

// Scratch (device globals; no allocation allowed)
__device__ int    g_dego[RN];                       // edge-only out-degree
__device__ int    g_degi[RN];                       // edge-only in-degree
__device__ int    g_off[RN + 1];
__device__ int    g_cur[RN];
__device__ int    g_part[RN];
__device__ int    g_bsum[SCAN_BLK];
__device__ int    g_eidx[RE];                       // CSR: src per (rel,dst)-bin
__device__ __half g_xw1h[(size_t)R * N * FHID];     // 38.4 MB (pre-scaled by rso)
__device__ float  g_acc[(size_t)N * FHID];          // 25.6 MB
__device__ __half g_xw2h[(size_t)R * N * FOUT];     // 19.2 MB (pre-scaled by rso)

// Side stream + events (host objects, created at load).
static cudaStream_t g_s1 = nullptr;
static cudaEvent_t  g_evA = nullptr, g_evB = nullptr;
namespace {
struct StreamInit {
    StreamInit() {
        cudaStreamCreateWithFlags(&g_s1, cudaStreamNonBlocking);
        cudaEventCreateWithFlags(&g_evA, cudaEventDisableTiming);
        cudaEventCreateWithFlags(&g_evB, cudaEventDisableTiming);
    }
} g_streaminit;
}

// ---------------- degrees ----------------
__global__ void k_deg_count(const int* __restrict__ src, const int* __restrict__ dst) {
    int i = blockIdx.x * blockDim.x + threadIdx.x;
    if (i < RE) {
        int r = i / E;
        atomicAdd(&g_dego[r * N + src[i]], 1);
        atomicAdd(&g_degi[r * N + dst[i]], 1);
    }
}

// ---------------- CSR build ----------------
__global__ __launch_bounds__(SCAN_BLK) void k_scan1() {
    __shared__ int s[SCAN_BLK];
    int t = threadIdx.x;
    int i = blockIdx.x * SCAN_BLK + t;
    int v = (i < RN) ? g_degi[i] : 0;
    s[t] = v;
    __syncthreads();
#pragma unroll
    for (int off = 1; off < SCAN_BLK; off <<= 1) {
        int u = (t >= off) ? s[t - off] : 0;
        __syncthreads();
        s[t] += u;
        __syncthreads();
    }
    if (i < RN) g_part[i] = s[t];
    if (t == SCAN_BLK - 1) g_bsum[blockIdx.x] = s[t];
}

__global__ __launch_bounds__(SCAN_BLK) void k_scan23() {
    __shared__ int s[SCAN_BLK];
    int t = threadIdx.x, bid = blockIdx.x;
    s[t] = (t < bid && t < NSCAN) ? g_bsum[t] : 0;
    __syncthreads();
#pragma unroll
    for (int off = SCAN_BLK / 2; off > 0; off >>= 1) {
        if (t < off) s[t] += s[t + off];
        __syncthreads();
    }
    int blockpref = s[0];
    int i = bid * SCAN_BLK + t;
    if (i < RN) {
        int excl = g_part[i] - g_degi[i] + blockpref;
        g_off[i] = excl;
        g_cur[i] = excl;
    }
    if (i == 0) g_off[RN] = RE;
}

__global__ void k_fill(const int* __restrict__ src, const int* __restrict__ dst) {
    int i = blockIdx.x * blockDim.x + threadIdx.x;
    if (i < RE) {
        int r = i / E;
        int pos = atomicAdd(&g_cur[r * N + dst[i]], 1);
        g_eidx[pos] = src[i];
    }
}

// ---------------- tf32 helpers ----------------
__device__ __forceinline__ uint32_t f2tf(float f) {
    uint32_t u;
    asm("cvt.rna.tf32.f32 %0, %1;" : "=r"(u) : "f"(f));
    return u;
}

__device__ __forceinline__ void mma_tf32(float* d,
        uint32_t a0, uint32_t a1, uint32_t a2, uint32_t a3,
        uint32_t b0, uint32_t b1) {
    asm volatile(
        "mma.sync.aligned.m16n8k8.row.col.f32.tf32.tf32.f32 "
        "{%0,%1,%2,%3}, {%4,%5,%6,%7}, {%8,%9}, {%0,%1,%2,%3};"
        : "+f"(d[0]), "+f"(d[1]), "+f"(d[2]), "+f"(d[3])
        : "r"(a0), "r"(a1), "r"(a2), "r"(a3), "r"(b0), "r"(b1));
}

// inline degree scaling: rsqrt(edge_degree + 1)
__device__ __forceinline__ float degscale(const int* deg, int idx) {
    return rsqrtf((float)(deg[idx] + 1));
}

// ---------------- tf32 GEMM F=128 -> fp16 out, pre-scaled by rso (inline) --------------
template<bool RELU>
__global__ __launch_bounds__(256)
void gemm_tc128(const float* __restrict__ A, const float* __restrict__ Wb,
                __half* __restrict__ Cb, int nrows) {
    constexpr int K = 128, BK = 32;
    const int r = blockIdx.y;
    const float* B = Wb + (size_t)r * K * 128;
    __half* C = Cb + (size_t)r * nrows * 128;
    const int row0 = blockIdx.x * 128;
    const int t = threadIdx.x;
    const int warp = t >> 5, lane = t & 31;
    const int qr = lane >> 2, qc = lane & 3;
    const int wm = (warp & 3) * 32;
    const int wn = (warp >> 2) * 64;

    __shared__ uint32_t sA[128][BK + 4];
    __shared__ uint32_t sB[BK][128 + 8];

    float acc[2][8][4];
#pragma unroll
    for (int i = 0; i < 2; i++)
#pragma unroll
        for (int j = 0; j < 8; j++)
#pragma unroll
            for (int q = 0; q < 4; q++) acc[i][j][q] = 0.f;

    const int am = t >> 1;
    const int ak = (t & 1) * 16;
    const int bkr = t >> 3;
    const int bnc = (t & 7) * 16;

    for (int k0 = 0; k0 < K; k0 += BK) {
        {
            int grow = row0 + am;
#pragma unroll
            for (int q = 0; q < 4; q++) {
                float4 v = make_float4(0.f, 0.f, 0.f, 0.f);
                if (grow < nrows)
                    v = *(const float4*)(A + (size_t)grow * K + k0 + ak + q * 4);
                if (RELU) {
                    v.x = fmaxf(v.x, 0.f); v.y = fmaxf(v.y, 0.f);
                    v.z = fmaxf(v.z, 0.f); v.w = fmaxf(v.w, 0.f);
                }
                uint4 u = make_uint4(f2tf(v.x), f2tf(v.y), f2tf(v.z), f2tf(v.w));
                *(uint4*)&sA[am][ak + q * 4] = u;
            }
        }
        {
#pragma unroll
            for (int q = 0; q < 4; q++) {
                float4 v = *(const float4*)(B + (size_t)(k0 + bkr) * 128 + bnc + q * 4);
                uint4 u = make_uint4(f2tf(v.x), f2tf(v.y), f2tf(v.z), f2tf(v.w));
                *(uint4*)&sB[bkr][bnc + q * 4] = u;
            }
        }
        __syncthreads();
#pragma unroll
        for (int kf = 0; kf < 4; kf++) {
            const int kb = kf * 8;
            uint32_t a[2][4];
#pragma unroll
            for (int mf = 0; mf < 2; mf++) {
                int rr = wm + mf * 16 + qr;
                a[mf][0] = sA[rr][kb + qc];
                a[mf][1] = sA[rr + 8][kb + qc];
                a[mf][2] = sA[rr][kb + qc + 4];
                a[mf][3] = sA[rr + 8][kb + qc + 4];
            }
#pragma unroll
            for (int nf = 0; nf < 8; nf++) {
                int nn = wn + nf * 8 + qr;
                uint32_t b0 = sB[kb + qc][nn];
                uint32_t b1 = sB[kb + qc + 4][nn];
                mma_tf32(acc[0][nf], a[0][0], a[0][1], a[0][2], a[0][3], b0, b1);
                mma_tf32(acc[1][nf], a[1][0], a[1][1], a[1][2], a[1][3], b0, b1);
            }
        }
        __syncthreads();
    }
#pragma unroll
    for (int mf = 0; mf < 2; mf++) {
        int r0g = row0 + wm + mf * 16 + qr;
        int r1g = r0g + 8;
        float s0 = (r0g < nrows) ? degscale(g_dego, r * N + r0g) : 0.f;
        float s1 = (r1g < nrows) ? degscale(g_dego, r * N + r1g) : 0.f;
#pragma unroll
        for (int nf = 0; nf < 8; nf++) {
            int col = wn + nf * 8 + qc * 2;
            if (r0g < nrows)
                *(__half2*)(C + (size_t)r0g * 128 + col) =
                    __floats2half2_rn(acc[mf][nf][0] * s0, acc[mf][nf][1] * s0);
            if (r1g < nrows)
                *(__half2*)(C + (size_t)r1g * 128 + col) =
                    __floats2half2_rn(acc[mf][nf][2] * s1, acc[mf][nf][3] * s1);
        }
    }
}

// ---------------- tf32 GEMM F=64 -> fp16 out, pre-scaled by rso (inline) ---------------
template<bool RELU>
__global__ __launch_bounds__(256)
void gemm_tc64(const float* __restrict__ A, const float* __restrict__ Wb,
               __half* __restrict__ Cb, int nrows) {
    constexpr int K = 128, BK = 32;
    const int r = blockIdx.y;
    const float* B = Wb + (size_t)r * K * 64;
    __half* C = Cb + (size_t)r * nrows * 64;
    const int row0 = blockIdx.x * 128;
    const int t = threadIdx.x;
    const int warp = t >> 5, lane = t & 31;
    const int qr = lane >> 2, qc = lane & 3;
    const int wm = (warp & 3) * 32;
    const int wn = (warp >> 2) * 32;

    __shared__ uint32_t sA[128][BK + 4];
    __shared__ uint32_t sB[BK][64 + 8];

    float acc[2][4][4];
#pragma unroll
    for (int i = 0; i < 2; i++)
#pragma unroll
        for (int j = 0; j < 4; j++)
#pragma unroll
            for (int q = 0; q < 4; q++) acc[i][j][q] = 0.f;

    const int am = t >> 1;
    const int ak = (t & 1) * 16;
    const int bkrow = t >> 3;
    const int bncol = (t & 7) * 8;

    for (int k0 = 0; k0 < K; k0 += BK) {
        {
            int grow = row0 + am;
#pragma unroll
            for (int q = 0; q < 4; q++) {
                float4 v = make_float4(0.f, 0.f, 0.f, 0.f);
                if (grow < nrows)
                    v = *(const float4*)(A + (size_t)grow * K + k0 + ak + q * 4);
                if (RELU) {
                    v.x = fmaxf(v.x, 0.f); v.y = fmaxf(v.y, 0.f);
                    v.z = fmaxf(v.z, 0.f); v.w = fmaxf(v.w, 0.f);
                }
                uint4 u = make_uint4(f2tf(v.x), f2tf(v.y), f2tf(v.z), f2tf(v.w));
                *(uint4*)&sA[am][ak + q * 4] = u;
            }
        }
        {
#pragma unroll
            for (int q = 0; q < 2; q++) {
                float4 v = *(const float4*)(B + (size_t)(k0 + bkrow) * 64 + bncol + q * 4);
                uint4 u = make_uint4(f2tf(v.x), f2tf(v.y), f2tf(v.z), f2tf(v.w));
                *(uint4*)&sB[bkrow][bncol + q * 4] = u;
            }
        }
        __syncthreads();
#pragma unroll
        for (int kf = 0; kf < 4; kf++) {
            const int kb = kf * 8;
            uint32_t a[2][4];
#pragma unroll
            for (int mf = 0; mf < 2; mf++) {
                int rr = wm + mf * 16 + qr;
                a[mf][0] = sA[rr][kb + qc];
                a[mf][1] = sA[rr + 8][kb + qc];
                a[mf][2] = sA[rr][kb + qc + 4];
                a[mf][3] = sA[rr + 8][kb + qc + 4];
            }
#pragma unroll
            for (int nf = 0; nf < 4; nf++) {
                int nn = wn + nf * 8 + qr;
                uint32_t b0 = sB[kb + qc][nn];
                uint32_t b1 = sB[kb + qc + 4][nn];
                mma_tf32(acc[0][nf], a[0][0], a[0][1], a[0][2], a[0][3], b0, b1);
                mma_tf32(acc[1][nf], a[1][0], a[1][1], a[1][2], a[1][3], b0, b1);
            }
        }
        __syncthreads();
    }
#pragma unroll
    for (int mf = 0; mf < 2; mf++) {
        int r0g = row0 + wm + mf * 16 + qr;
        int r1g = r0g + 8;
        float s0 = (r0g < nrows) ? degscale(g_dego, r * N + r0g) : 0.f;
        float s1 = (r1g < nrows) ? degscale(g_dego, r * N + r1g) : 0.f;
#pragma unroll
        for (int nf = 0; nf < 4; nf++) {
            int col = wn + nf * 8 + qc * 2;
            if (r0g < nrows)
                *(__half2*)(C + (size_t)r0g * 64 + col) =
                    __floats2half2_rn(acc[mf][nf][0] * s0, acc[mf][nf][1] * s0);
            if (r1g < nrows)
                *(__half2*)(C + (size_t)r1g * 64 + col) =
                    __floats2half2_rn(acc[mf][nf][2] * s1, acc[mf][nf][3] * s1);
        }
    }
}

// ---------------- fused gather + selfloop + bias, F=128 (r7 form: unroll 4) ------------
__global__ __launch_bounds__(256)
void k_gather128(const __half* __restrict__ xw, const float* __restrict__ b,
                 float* __restrict__ out) {
    int w = (blockIdx.x * blockDim.x + threadIdx.x) >> 5;
    int lane = threadIdx.x & 31;
    if (w >= N) return;
    int c = lane * 4;

    float4 b0 = *(const float4*)(b + 0 * FHID + c);
    float4 b1 = *(const float4*)(b + 1 * FHID + c);
    float4 b2 = *(const float4*)(b + 2 * FHID + c);
    float4 tot = make_float4(b0.x + b1.x + b2.x, b0.y + b1.y + b2.y,
                             b0.z + b1.z + b2.z, b0.w + b1.w + b2.w);

#pragma unroll
    for (int r = 0; r < R; r++) {
        const int bin = r * N + w;
        const __half* base = xw + (size_t)r * N * FHID;
        float4 a = make_float4(0.f, 0.f, 0.f, 0.f);
        int j0 = g_off[bin], j1 = g_off[bin + 1];
        int j = j0;
        for (; j + 4 <= j1; j += 4) {
            int s0 = __ldg(&g_eidx[j + 0]);
            int s1 = __ldg(&g_eidx[j + 1]);
            int s2 = __ldg(&g_eidx[j + 2]);
            int s3 = __ldg(&g_eidx[j + 3]);
            uint2 u0 = *(const uint2*)(base + (size_t)s0 * FHID + c);
            uint2 u1 = *(const uint2*)(base + (size_t)s1 * FHID + c);
            uint2 u2 = *(const uint2*)(base + (size_t)s2 * FHID + c);
            uint2 u3 = *(const uint2*)(base + (size_t)s3 * FHID + c);
#pragma unroll
            for (int p = 0; p < 4; p++) {
                uint2 u = (p == 0) ? u0 : (p == 1) ? u1 : (p == 2) ? u2 : u3;
                float2 f0 = __half22float2(*reinterpret_cast<__half2*>(&u.x));
                float2 f1 = __half22float2(*reinterpret_cast<__half2*>(&u.y));
                a.x += f0.x; a.y += f0.y; a.z += f1.x; a.w += f1.y;
            }
        }
        for (; j < j1; j++) {
            int s = __ldg(&g_eidx[j]);
            uint2 u = *(const uint2*)(base + (size_t)s * FHID + c);
            float2 f0 = __half22float2(*reinterpret_cast<__half2*>(&u.x));
            float2 f1 = __half22float2(*reinterpret_cast<__half2*>(&u.y));
            a.x += f0.x; a.y += f0.y; a.z += f1.x; a.w += f1.y;
        }
        // self-loop: pre-scaled row already carries rso[w]
        {
            uint2 u = *(const uint2*)(base + (size_t)w * FHID + c);
            float2 f0 = __half22float2(*reinterpret_cast<__half2*>(&u.x));
            float2 f1 = __half22float2(*reinterpret_cast<__half2*>(&u.y));
            a.x += f0.x; a.y += f0.y; a.z += f1.x; a.w += f1.y;
        }
        float ri = degscale(g_degi, bin);
        tot.x = fmaf(ri, a.x, tot.x); tot.y = fmaf(ri, a.y, tot.y);
        tot.z = fmaf(ri, a.z, tot.z); tot.w = fmaf(ri, a.w, tot.w);
    }
    *(float4*)(out + (size_t)w * FHID + c) = tot;
}

// ---------------- fused gather + selfloop + bias, F=64 (r7 form: 2 nodes/warp) ---------
__global__ __launch_bounds__(256)
void k_gather64(const __half* __restrict__ xw, const float* __restrict__ b,
                float* __restrict__ out) {
    int warp = (blockIdx.x * blockDim.x + threadIdx.x) >> 5;
    int lane = threadIdx.x & 31;
    int w = warp * 2 + (lane >> 4);
    if (w >= N) return;
    int c = (lane & 15) * 4;

    float4 b0 = *(const float4*)(b + 0 * FOUT + c);
    float4 b1 = *(const float4*)(b + 1 * FOUT + c);
    float4 b2 = *(const float4*)(b + 2 * FOUT + c);
    float4 tot = make_float4(b0.x + b1.x + b2.x, b0.y + b1.y + b2.y,
                             b0.z + b1.z + b2.z, b0.w + b1.w + b2.w);

#pragma unroll
    for (int r = 0; r < R; r++) {
        const int bin = r * N + w;
        const __half* base = xw + (size_t)r * N * FOUT;
        float4 a = make_float4(0.f, 0.f, 0.f, 0.f);
        int j0 = g_off[bin], j1 = g_off[bin + 1];
        int j = j0;
        for (; j + 4 <= j1; j += 4) {
            int s0 = __ldg(&g_eidx[j + 0]);
            int s1 = __ldg(&g_eidx[j + 1]);
            int s2 = __ldg(&g_eidx[j + 2]);
            int s3 = __ldg(&g_eidx[j + 3]);
            uint2 u0 = *(const uint2*)(base + (size_t)s0 * FOUT + c);
            uint2 u1 = *(const uint2*)(base + (size_t)s1 * FOUT + c);
            uint2 u2 = *(const uint2*)(base + (size_t)s2 * FOUT + c);
            uint2 u3 = *(const uint2*)(base + (size_t)s3 * FOUT + c);
#pragma unroll
            for (int p = 0; p < 4; p++) {
                uint2 u = (p == 0) ? u0 : (p == 1) ? u1 : (p == 2) ? u2 : u3;
                float2 f0 = __half22float2(*reinterpret_cast<__half2*>(&u.x));
                float2 f1 = __half22float2(*reinterpret_cast<__half2*>(&u.y));
                a.x += f0.x; a.y += f0.y; a.z += f1.x; a.w += f1.y;
            }
        }
        for (; j < j1; j++) {
            int s = __ldg(&g_eidx[j]);
            uint2 u = *(const uint2*)(base + (size_t)s * FOUT + c);
            float2 f0 = __half22float2(*reinterpret_cast<__half2*>(&u.x));
            float2 f1 = __half22float2(*reinterpret_cast<__half2*>(&u.y));
            a.x += f0.x; a.y += f0.y; a.z += f1.x; a.w += f1.y;
        }
        {
            uint2 u = *(const uint2*)(base + (size_t)w * FOUT + c);
            float2 f0 = __half22float2(*reinterpret_cast<__half2*>(&u.x));
            float2 f1 = __half22float2(*reinterpret_cast<__half2*>(&u.y));
            a.x += f0.x; a.y += f0.y; a.z += f1.x; a.w += f1.y;
        }
        float ri = degscale(g_degi, bin);
        tot.x = fmaf(ri, a.x, tot.x); tot.y = fmaf(ri, a.y, tot.y);
        tot.z = fmaf(ri, a.z, tot.z); tot.w = fmaf(ri, a.w, tot.w);
    }
    *(float4*)(out + (size_t)w * FOUT + c) = tot;
}

// ---------------- launch ----------------
extern "C" void kernel_launch(void* const* d_in, const int* in_sizes, int n_in,
                              void* d_out, int out_size) {
    const float* x   = (const float*)d_in[0];
    const int*   src = (const int*)d_in[1];
    const int*   dst = (const int*)d_in[2];
    const float* W1  = (const float*)d_in[3];
    const float* b1  = (const float*)d_in[4];
    const float* W2  = (const float*)d_in[5];
    const float* b2  = (const float*)d_in[6];
    float* out = (float*)d_out;

    __half *xw1, *xw2;
    float *acc;
    int *dego, *degi;
    cudaGetSymbolAddress((void**)&xw1, g_xw1h);
    cudaGetSymbolAddress((void**)&acc, g_acc);
    cudaGetSymbolAddress((void**)&xw2, g_xw2h);
    cudaGetSymbolAddress((void**)&dego, g_dego);
    cudaGetSymbolAddress((void**)&degi, g_degi);

    const bool fork = (g_s1 != nullptr && g_evA != nullptr && g_evB != nullptr);
    cudaStream_t sb = fork ? g_s1 : (cudaStream_t)0;

    // degrees (main stream)
    cudaMemsetAsync(dego, 0, RN * sizeof(int), 0);
    cudaMemsetAsync(degi, 0, RN * sizeof(int), 0);
    k_deg_count<<<(RE + 255) / 256, 256>>>(src, dst);

    // fork: CSR build (scan + fill) on side stream, overlapped with GEMM1
    if (fork) {
        cudaEventRecord(g_evA, 0);
        cudaStreamWaitEvent(sb, g_evA, 0);
    }
    k_scan1<<<NSCAN, SCAN_BLK, 0, sb>>>();
    k_scan23<<<NSCAN, SCAN_BLK, 0, sb>>>();
    k_fill<<<(RE + 255) / 256, 256, 0, sb>>>(src, dst);
    if (fork) cudaEventRecord(g_evB, sb);

    // main stream: GEMM1 directly (degree scaling computed inline in epilogue)
    dim3 gg((N + 127) / 128, R);
    gemm_tc128<false><<<gg, 256>>>(x, W1, xw1, N);

    // join: gathers need the CSR
    if (fork) cudaStreamWaitEvent((cudaStream_t)0, g_evB, 0);
    k_gather128<<<(N * 32 + 255) / 256, 256>>>(xw1, b1, acc);

    // layer 2
    gemm_tc64<true><<<gg, 256>>>(acc, W2, xw2, N);
    k_gather64<<<(N * 16 + 255) / 256, 256>>>(xw2, b2, out);
}

// round 17
// speedup vs baseline: 1.0485x; 1.0235x over previous
#include <cuda_runtime.h>
#include <cuda_fp16.h>
#include <cstdint>

// Problem constants (fixed by the dataset)
constexpr int N  = 50000;
constexpr int E  = 800000;
constexpr int R  = 3;
constexpr int FHID = 128;
constexpr int FOUT = 64;
constexpr int RN = R * N;
constexpr int RE = R * E;

constexpr int SCAN_BLK = 512;
constexpr int NSCAN = (RN + SCAN_BLK - 1) / SCAN_BLK;   // 293

// Scratch (device globals; no allocation allowed)
__device__ int    g_dego[RN];                       // edge-only out-degree
__device__ int    g_degi[RN];                       // edge-only in-degree
__device__ int    g_off[RN + 1];
__device__ int    g_cur[RN];
__device__ int    g_part[RN];
__device__ int    g_bsum[SCAN_BLK];
__device__ int    g_eidx[RE];                       // CSR: src per (rel,dst)-bin
__device__ __half g_xw1h[(size_t)R * N * FHID];     // 38.4 MB (pre-scaled by rso)
__device__ __half g_acch[(size_t)N * FHID];         // 12.8 MB (layer-1 output, fp16)
__device__ __half g_xw2h[(size_t)R * N * FOUT];     // 19.2 MB (pre-scaled by rso)

// Side stream + events (host objects, created at load).
static cudaStream_t g_s1 = nullptr;
static cudaEvent_t  g_evA = nullptr, g_evB = nullptr;
namespace {
struct StreamInit {
    StreamInit() {
        cudaStreamCreateWithFlags(&g_s1, cudaStreamNonBlocking);
        cudaEventCreateWithFlags(&g_evA, cudaEventDisableTiming);
        cudaEventCreateWithFlags(&g_evB, cudaEventDisableTiming);
    }
} g_streaminit;
}

// ---------------- degrees ----------------
__global__ void k_deg_count(const int* __restrict__ src, const int* __restrict__ dst) {
    int i = blockIdx.x * blockDim.x + threadIdx.x;
    if (i < RE) {
        int r = i / E;
        atomicAdd(&g_dego[r * N + src[i]], 1);
        atomicAdd(&g_degi[r * N + dst[i]], 1);
    }
}

// ---------------- CSR build ----------------
__global__ __launch_bounds__(SCAN_BLK) void k_scan1() {
    __shared__ int s[SCAN_BLK];
    int t = threadIdx.x;
    int i = blockIdx.x * SCAN_BLK + t;
    int v = (i < RN) ? g_degi[i] : 0;
    s[t] = v;
    __syncthreads();
#pragma unroll
    for (int off = 1; off < SCAN_BLK; off <<= 1) {
        int u = (t >= off) ? s[t - off] : 0;
        __syncthreads();
        s[t] += u;
        __syncthreads();
    }
    if (i < RN) g_part[i] = s[t];
    if (t == SCAN_BLK - 1) g_bsum[blockIdx.x] = s[t];
}

__global__ __launch_bounds__(SCAN_BLK) void k_scan23() {
    __shared__ int s[SCAN_BLK];
    int t = threadIdx.x, bid = blockIdx.x;
    s[t] = (t < bid && t < NSCAN) ? g_bsum[t] : 0;
    __syncthreads();
#pragma unroll
    for (int off = SCAN_BLK / 2; off > 0; off >>= 1) {
        if (t < off) s[t] += s[t + off];
        __syncthreads();
    }
    int blockpref = s[0];
    int i = bid * SCAN_BLK + t;
    if (i < RN) {
        int excl = g_part[i] - g_degi[i] + blockpref;
        g_off[i] = excl;
        g_cur[i] = excl;
    }
    if (i == 0) g_off[RN] = RE;
}

__global__ void k_fill(const int* __restrict__ src, const int* __restrict__ dst) {
    int i = blockIdx.x * blockDim.x + threadIdx.x;
    if (i < RE) {
        int r = i / E;
        int pos = atomicAdd(&g_cur[r * N + dst[i]], 1);
        g_eidx[pos] = src[i];
    }
}

// ---------------- tf32 helpers ----------------
__device__ __forceinline__ uint32_t f2tf(float f) {
    uint32_t u;
    asm("cvt.rna.tf32.f32 %0, %1;" : "=r"(u) : "f"(f));
    return u;
}

__device__ __forceinline__ void mma_tf32(float* d,
        uint32_t a0, uint32_t a1, uint32_t a2, uint32_t a3,
        uint32_t b0, uint32_t b1) {
    asm volatile(
        "mma.sync.aligned.m16n8k8.row.col.f32.tf32.tf32.f32 "
        "{%0,%1,%2,%3}, {%4,%5,%6,%7}, {%8,%9}, {%0,%1,%2,%3};"
        : "+f"(d[0]), "+f"(d[1]), "+f"(d[2]), "+f"(d[3])
        : "r"(a0), "r"(a1), "r"(a2), "r"(a3), "r"(b0), "r"(b1));
}

// inline degree scaling: rsqrt(edge_degree + 1)
__device__ __forceinline__ float degscale(const int* deg, int idx) {
    return rsqrtf((float)(deg[idx] + 1));
}

// ---------------- tf32 GEMM F=128 (fp32 in) -> fp16 out, pre-scaled by rso -------------
__global__ __launch_bounds__(256)
void gemm_tc128(const float* __restrict__ A, const float* __restrict__ Wb,
                __half* __restrict__ Cb, int nrows) {
    constexpr int K = 128, BK = 32;
    const int r = blockIdx.y;
    const float* B = Wb + (size_t)r * K * 128;
    __half* C = Cb + (size_t)r * nrows * 128;
    const int row0 = blockIdx.x * 128;
    const int t = threadIdx.x;
    const int warp = t >> 5, lane = t & 31;
    const int qr = lane >> 2, qc = lane & 3;
    const int wm = (warp & 3) * 32;
    const int wn = (warp >> 2) * 64;

    __shared__ uint32_t sA[128][BK + 4];
    __shared__ uint32_t sB[BK][128 + 8];

    float acc[2][8][4];
#pragma unroll
    for (int i = 0; i < 2; i++)
#pragma unroll
        for (int j = 0; j < 8; j++)
#pragma unroll
            for (int q = 0; q < 4; q++) acc[i][j][q] = 0.f;

    const int am = t >> 1;
    const int ak = (t & 1) * 16;
    const int bkr = t >> 3;
    const int bnc = (t & 7) * 16;

    for (int k0 = 0; k0 < K; k0 += BK) {
        {
            int grow = row0 + am;
#pragma unroll
            for (int q = 0; q < 4; q++) {
                float4 v = make_float4(0.f, 0.f, 0.f, 0.f);
                if (grow < nrows)
                    v = *(const float4*)(A + (size_t)grow * K + k0 + ak + q * 4);
                uint4 u = make_uint4(f2tf(v.x), f2tf(v.y), f2tf(v.z), f2tf(v.w));
                *(uint4*)&sA[am][ak + q * 4] = u;
            }
        }
        {
#pragma unroll
            for (int q = 0; q < 4; q++) {
                float4 v = *(const float4*)(B + (size_t)(k0 + bkr) * 128 + bnc + q * 4);
                uint4 u = make_uint4(f2tf(v.x), f2tf(v.y), f2tf(v.z), f2tf(v.w));
                *(uint4*)&sB[bkr][bnc + q * 4] = u;
            }
        }
        __syncthreads();
#pragma unroll
        for (int kf = 0; kf < 4; kf++) {
            const int kb = kf * 8;
            uint32_t a[2][4];
#pragma unroll
            for (int mf = 0; mf < 2; mf++) {
                int rr = wm + mf * 16 + qr;
                a[mf][0] = sA[rr][kb + qc];
                a[mf][1] = sA[rr + 8][kb + qc];
                a[mf][2] = sA[rr][kb + qc + 4];
                a[mf][3] = sA[rr + 8][kb + qc + 4];
            }
#pragma unroll
            for (int nf = 0; nf < 8; nf++) {
                int nn = wn + nf * 8 + qr;
                uint32_t b0 = sB[kb + qc][nn];
                uint32_t b1 = sB[kb + qc + 4][nn];
                mma_tf32(acc[0][nf], a[0][0], a[0][1], a[0][2], a[0][3], b0, b1);
                mma_tf32(acc[1][nf], a[1][0], a[1][1], a[1][2], a[1][3], b0, b1);
            }
        }
        __syncthreads();
    }
#pragma unroll
    for (int mf = 0; mf < 2; mf++) {
        int r0g = row0 + wm + mf * 16 + qr;
        int r1g = r0g + 8;
        float s0 = (r0g < nrows) ? degscale(g_dego, r * N + r0g) : 0.f;
        float s1 = (r1g < nrows) ? degscale(g_dego, r * N + r1g) : 0.f;
#pragma unroll
        for (int nf = 0; nf < 8; nf++) {
            int col = wn + nf * 8 + qc * 2;
            if (r0g < nrows)
                *(__half2*)(C + (size_t)r0g * 128 + col) =
                    __floats2half2_rn(acc[mf][nf][0] * s0, acc[mf][nf][1] * s0);
            if (r1g < nrows)
                *(__half2*)(C + (size_t)r1g * 128 + col) =
                    __floats2half2_rn(acc[mf][nf][2] * s1, acc[mf][nf][3] * s1);
        }
    }
}

// ---------------- tf32 GEMM F=64 (fp16 in, relu) -> fp16 out, pre-scaled by rso --------
__global__ __launch_bounds__(256)
void gemm_tc64(const __half* __restrict__ A, const float* __restrict__ Wb,
               __half* __restrict__ Cb, int nrows) {
    constexpr int K = 128, BK = 32;
    const int r = blockIdx.y;
    const float* B = Wb + (size_t)r * K * 64;
    __half* C = Cb + (size_t)r * nrows * 64;
    const int row0 = blockIdx.x * 128;
    const int t = threadIdx.x;
    const int warp = t >> 5, lane = t & 31;
    const int qr = lane >> 2, qc = lane & 3;
    const int wm = (warp & 3) * 32;
    const int wn = (warp >> 2) * 32;

    __shared__ uint32_t sA[128][BK + 4];
    __shared__ uint32_t sB[BK][64 + 8];

    float acc[2][4][4];
#pragma unroll
    for (int i = 0; i < 2; i++)
#pragma unroll
        for (int j = 0; j < 4; j++)
#pragma unroll
            for (int q = 0; q < 4; q++) acc[i][j][q] = 0.f;

    const int am = t >> 1;
    const int ak = (t & 1) * 16;
    const int bkrow = t >> 3;
    const int bncol = (t & 7) * 8;

    for (int k0 = 0; k0 < K; k0 += BK) {
        {
            int grow = row0 + am;
            uint4 p0 = make_uint4(0, 0, 0, 0), p1 = p0;
            if (grow < nrows) {
                const __half* ar = A + (size_t)grow * K + k0 + ak;
                p0 = *(const uint4*)ar;
                p1 = *(const uint4*)(ar + 8);
            }
#pragma unroll
            for (int h = 0; h < 2; h++) {
                uint4 p = h ? p1 : p0;
                const uint32_t* pw = reinterpret_cast<const uint32_t*>(&p);
#pragma unroll
                for (int q = 0; q < 4; q++) {
                    float2 f = __half22float2(*reinterpret_cast<const __half2*>(&pw[q]));
                    sA[am][ak + h * 8 + q * 2 + 0] = f2tf(fmaxf(f.x, 0.f));
                    sA[am][ak + h * 8 + q * 2 + 1] = f2tf(fmaxf(f.y, 0.f));
                }
            }
        }
        {
#pragma unroll
            for (int q = 0; q < 2; q++) {
                float4 v = *(const float4*)(B + (size_t)(k0 + bkrow) * 64 + bncol + q * 4);
                uint4 u = make_uint4(f2tf(v.x), f2tf(v.y), f2tf(v.z), f2tf(v.w));
                *(uint4*)&sB[bkrow][bncol + q * 4] = u;
            }
        }
        __syncthreads();
#pragma unroll
        for (int kf = 0; kf < 4; kf++) {
            const int kb = kf * 8;
            uint32_t a[2][4];
#pragma unroll
            for (int mf = 0; mf < 2; mf++) {
                int rr = wm + mf * 16 + qr;
                a[mf][0] = sA[rr][kb + qc];
                a[mf][1] = sA[rr + 8][kb + qc];
                a[mf][2] = sA[rr][kb + qc + 4];
                a[mf][3] = sA[rr + 8][kb + qc + 4];
            }
#pragma unroll
            for (int nf = 0; nf < 4; nf++) {
                int nn = wn + nf * 8 + qr;
                uint32_t b0 = sB[kb + qc][nn];
                uint32_t b1 = sB[kb + qc + 4][nn];
                mma_tf32(acc[0][nf], a[0][0], a[0][1], a[0][2], a[0][3], b0, b1);
                mma_tf32(acc[1][nf], a[1][0], a[1][1], a[1][2], a[1][3], b0, b1);
            }
        }
        __syncthreads();
    }
#pragma unroll
    for (int mf = 0; mf < 2; mf++) {
        int r0g = row0 + wm + mf * 16 + qr;
        int r1g = r0g + 8;
        float s0 = (r0g < nrows) ? degscale(g_dego, r * N + r0g) : 0.f;
        float s1 = (r1g < nrows) ? degscale(g_dego, r * N + r1g) : 0.f;
#pragma unroll
        for (int nf = 0; nf < 4; nf++) {
            int col = wn + nf * 8 + qc * 2;
            if (r0g < nrows)
                *(__half2*)(C + (size_t)r0g * 64 + col) =
                    __floats2half2_rn(acc[mf][nf][0] * s0, acc[mf][nf][1] * s0);
            if (r1g < nrows)
                *(__half2*)(C + (size_t)r1g * 64 + col) =
                    __floats2half2_rn(acc[mf][nf][2] * s1, acc[mf][nf][3] * s1);
        }
    }
}

// ---------------- fused gather + selfloop + bias, F=128 (r7 form) -> fp16 out ----------
__global__ __launch_bounds__(256)
void k_gather128(const __half* __restrict__ xw, const float* __restrict__ b,
                 __half* __restrict__ out) {
    int w = (blockIdx.x * blockDim.x + threadIdx.x) >> 5;
    int lane = threadIdx.x & 31;
    if (w >= N) return;
    int c = lane * 4;

    float4 b0 = *(const float4*)(b + 0 * FHID + c);
    float4 b1 = *(const float4*)(b + 1 * FHID + c);
    float4 b2 = *(const float4*)(b + 2 * FHID + c);
    float4 tot = make_float4(b0.x + b1.x + b2.x, b0.y + b1.y + b2.y,
                             b0.z + b1.z + b2.z, b0.w + b1.w + b2.w);

#pragma unroll
    for (int r = 0; r < R; r++) {
        const int bin = r * N + w;
        const __half* base = xw + (size_t)r * N * FHID;
        float4 a = make_float4(0.f, 0.f, 0.f, 0.f);
        int j0 = g_off[bin], j1 = g_off[bin + 1];
        int j = j0;
        for (; j + 4 <= j1; j += 4) {
            int s0 = __ldg(&g_eidx[j + 0]);
            int s1 = __ldg(&g_eidx[j + 1]);
            int s2 = __ldg(&g_eidx[j + 2]);
            int s3 = __ldg(&g_eidx[j + 3]);
            uint2 u0 = *(const uint2*)(base + (size_t)s0 * FHID + c);
            uint2 u1 = *(const uint2*)(base + (size_t)s1 * FHID + c);
            uint2 u2 = *(const uint2*)(base + (size_t)s2 * FHID + c);
            uint2 u3 = *(const uint2*)(base + (size_t)s3 * FHID + c);
#pragma unroll
            for (int p = 0; p < 4; p++) {
                uint2 u = (p == 0) ? u0 : (p == 1) ? u1 : (p == 2) ? u2 : u3;
                float2 f0 = __half22float2(*reinterpret_cast<__half2*>(&u.x));
                float2 f1 = __half22float2(*reinterpret_cast<__half2*>(&u.y));
                a.x += f0.x; a.y += f0.y; a.z += f1.x; a.w += f1.y;
            }
        }
        for (; j < j1; j++) {
            int s = __ldg(&g_eidx[j]);
            uint2 u = *(const uint2*)(base + (size_t)s * FHID + c);
            float2 f0 = __half22float2(*reinterpret_cast<__half2*>(&u.x));
            float2 f1 = __half22float2(*reinterpret_cast<__half2*>(&u.y));
            a.x += f0.x; a.y += f0.y; a.z += f1.x; a.w += f1.y;
        }
        // self-loop: pre-scaled row already carries rso[w]
        {
            uint2 u = *(const uint2*)(base + (size_t)w * FHID + c);
            float2 f0 = __half22float2(*reinterpret_cast<__half2*>(&u.x));
            float2 f1 = __half22float2(*reinterpret_cast<__half2*>(&u.y));
            a.x += f0.x; a.y += f0.y; a.z += f1.x; a.w += f1.y;
        }
        float ri = degscale(g_degi, bin);
        tot.x = fmaf(ri, a.x, tot.x); tot.y = fmaf(ri, a.y, tot.y);
        tot.z = fmaf(ri, a.z, tot.z); tot.w = fmaf(ri, a.w, tot.w);
    }
    __half2 o0 = __floats2half2_rn(tot.x, tot.y);
    __half2 o1 = __floats2half2_rn(tot.z, tot.w);
    uint2 o;
    o.x = *reinterpret_cast<uint32_t*>(&o0);
    o.y = *reinterpret_cast<uint32_t*>(&o1);
    *(uint2*)(out + (size_t)w * FHID + c) = o;
}

// ---------------- fused gather + selfloop + bias, F=64 (r7 form: 2 nodes/warp) ---------
__global__ __launch_bounds__(256)
void k_gather64(const __half* __restrict__ xw, const float* __restrict__ b,
                float* __restrict__ out) {
    int warp = (blockIdx.x * blockDim.x + threadIdx.x) >> 5;
    int lane = threadIdx.x & 31;
    int w = warp * 2 + (lane >> 4);
    if (w >= N) return;
    int c = (lane & 15) * 4;

    float4 b0 = *(const float4*)(b + 0 * FOUT + c);
    float4 b1 = *(const float4*)(b + 1 * FOUT + c);
    float4 b2 = *(const float4*)(b + 2 * FOUT + c);
    float4 tot = make_float4(b0.x + b1.x + b2.x, b0.y + b1.y + b2.y,
                             b0.z + b1.z + b2.z, b0.w + b1.w + b2.w);

#pragma unroll
    for (int r = 0; r < R; r++) {
        const int bin = r * N + w;
        const __half* base = xw + (size_t)r * N * FOUT;
        float4 a = make_float4(0.f, 0.f, 0.f, 0.f);
        int j0 = g_off[bin], j1 = g_off[bin + 1];
        int j = j0;
        for (; j + 4 <= j1; j += 4) {
            int s0 = __ldg(&g_eidx[j + 0]);
            int s1 = __ldg(&g_eidx[j + 1]);
            int s2 = __ldg(&g_eidx[j + 2]);
            int s3 = __ldg(&g_eidx[j + 3]);
            uint2 u0 = *(const uint2*)(base + (size_t)s0 * FOUT + c);
            uint2 u1 = *(const uint2*)(base + (size_t)s1 * FOUT + c);
            uint2 u2 = *(const uint2*)(base + (size_t)s2 * FOUT + c);
            uint2 u3 = *(const uint2*)(base + (size_t)s3 * FOUT + c);
#pragma unroll
            for (int p = 0; p < 4; p++) {
                uint2 u = (p == 0) ? u0 : (p == 1) ? u1 : (p == 2) ? u2 : u3;
                float2 f0 = __half22float2(*reinterpret_cast<__half2*>(&u.x));
                float2 f1 = __half22float2(*reinterpret_cast<__half2*>(&u.y));
                a.x += f0.x; a.y += f0.y; a.z += f1.x; a.w += f1.y;
            }
        }
        for (; j < j1; j++) {
            int s = __ldg(&g_eidx[j]);
            uint2 u = *(const uint2*)(base + (size_t)s * FOUT + c);
            float2 f0 = __half22float2(*reinterpret_cast<__half2*>(&u.x));
            float2 f1 = __half22float2(*reinterpret_cast<__half2*>(&u.y));
            a.x += f0.x; a.y += f0.y; a.z += f1.x; a.w += f1.y;
        }
        {
            uint2 u = *(const uint2*)(base + (size_t)w * FOUT + c);
            float2 f0 = __half22float2(*reinterpret_cast<__half2*>(&u.x));
            float2 f1 = __half22float2(*reinterpret_cast<__half2*>(&u.y));
            a.x += f0.x; a.y += f0.y; a.z += f1.x; a.w += f1.y;
        }
        float ri = degscale(g_degi, bin);
        tot.x = fmaf(ri, a.x, tot.x); tot.y = fmaf(ri, a.y, tot.y);
        tot.z = fmaf(ri, a.z, tot.z); tot.w = fmaf(ri, a.w, tot.w);
    }
    *(float4*)(out + (size_t)w * FOUT + c) = tot;
}

// ---------------- launch ----------------
extern "C" void kernel_launch(void* const* d_in, const int* in_sizes, int n_in,
                              void* d_out, int out_size) {
    const float* x   = (const float*)d_in[0];
    const int*   src = (const int*)d_in[1];
    const int*   dst = (const int*)d_in[2];
    const float* W1  = (const float*)d_in[3];
    const float* b1  = (const float*)d_in[4];
    const float* W2  = (const float*)d_in[5];
    const float* b2  = (const float*)d_in[6];
    float* out = (float*)d_out;

    __half *xw1, *xw2, *acc;
    int *dego, *degi;
    cudaGetSymbolAddress((void**)&xw1, g_xw1h);
    cudaGetSymbolAddress((void**)&acc, g_acch);
    cudaGetSymbolAddress((void**)&xw2, g_xw2h);
    cudaGetSymbolAddress((void**)&dego, g_dego);
    cudaGetSymbolAddress((void**)&degi, g_degi);

    const bool fork = (g_s1 != nullptr && g_evA != nullptr && g_evB != nullptr);
    cudaStream_t sb = fork ? g_s1 : (cudaStream_t)0;

    // degrees (main stream)
    cudaMemsetAsync(dego, 0, RN * sizeof(int), 0);
    cudaMemsetAsync(degi, 0, RN * sizeof(int), 0);
    k_deg_count<<<(RE + 255) / 256, 256>>>(src, dst);

    // fork: CSR build (scan + fill) on side stream, overlapped with GEMM1
    if (fork) {
        cudaEventRecord(g_evA, 0);
        cudaStreamWaitEvent(sb, g_evA, 0);
    }
    k_scan1<<<NSCAN, SCAN_BLK, 0, sb>>>();
    k_scan23<<<NSCAN, SCAN_BLK, 0, sb>>>();
    k_fill<<<(RE + 255) / 256, 256, 0, sb>>>(src, dst);
    if (fork) cudaEventRecord(g_evB, sb);

    // main stream: GEMM1 (degree scaling computed inline in epilogue)
    dim3 gg((N + 127) / 128, R);
    gemm_tc128<<<gg, 256>>>(x, W1, xw1, N);

    // join: gathers need the CSR
    if (fork) cudaStreamWaitEvent((cudaStream_t)0, g_evB, 0);
    k_gather128<<<(N * 32 + 255) / 256, 256>>>(xw1, b1, acc);

    // layer 2
    gemm_tc64<<<gg, 256>>>(acc, W2, xw2, N);
    k_gather64<<<(N * 16 + 255) / 256, 256>>>(xw2, b2, out);
}